// round 10
// baseline (speedup 1.0000x reference)
#include <cuda_runtime.h>
#include <cuda_bf16.h>
#include <math.h>
#include <stdint.h>

#define TT 512
#define BB 64
#define HH 1024
#define G3 3072   // 3*H
#define LL 2
#define RB 128         // recurrence blocks, 1/SM, each owns 8 output columns j

// ---- int8 recurrence smem layout (bytes) ----
#define WROW8   1040                 // W int8 smem row stride (1024 + 16) -> conflict-free
#define HROW8   144                  // h chunk smem row stride (128 + 16)
#define OFF8_WB (24 * WROW8)         // 24960  (Wa rows at 0)
#define OFF8_H  (48 * WROW8)         // 49920
#define HBUF8   (2 * 64 * HROW8)     // 18432 per buffer (ha 9216 + hb 9216)
#define OFF8_ACC (OFF8_H + 4 * HBUF8)        // 123648
#define SMEM8   (OFF8_ACC + 2 * 64 * 26 * 4) // 136960

// fixed-point scales
#define WSCALE  1044224.0f           // |W|<=1/32 -> |W16| <= 32632 (no clamp needed)
#define HSCALE  4096.0f              // h range +-8 at 16 bits

// ---------------- scratch (static device arrays; no cudaMalloc) -------------
__device__ float g_xg[(size_t)TT * BB * G3];          // input gates, current layer
__device__ float g_y1[(size_t)TT * BB * HH];          // layer-1 output sequence
__device__ __nv_bfloat16 g_xhi[(size_t)TT * BB * HH]; // split X (hi)
__device__ __nv_bfloat16 g_xlo[(size_t)TT * BB * HH]; // split X (lo)
__device__ __nv_bfloat16 g_whi[(size_t)G3 * HH];      // split Wih (hi)
__device__ __nv_bfloat16 g_wlo[(size_t)G3 * HH];      // split Wih (lo)
__device__ int8_t g_wa8[(size_t)G3 * HH];             // Whh high int8 plane
__device__ int8_t g_wb8[(size_t)G3 * HH];             // Whh low  int8 plane (signed)
__device__ int8_t g_ha8[2][BB * HH];                  // ping-pong h high plane [b][k]
__device__ int8_t g_hb8[2][BB * HH];                  // ping-pong h low  plane [b][k]

// grid-barrier state
__device__ unsigned g_bar_count = 0;
__device__ unsigned g_bar_gen   = 0;

__global__ void bar_reset_kernel() { g_bar_count = 0; }

// ======================= PTX helpers ==========================================
__device__ __forceinline__ uint32_t smem_u32(const void* p) {
    uint32_t a;
    asm("{ .reg .u64 t; cvta.to.shared.u64 t, %1; cvt.u32.u64 %0, t; }"
        : "=r"(a) : "l"(p));
    return a;
}
__device__ __forceinline__ void ldmx4(uint32_t* r, uint32_t addr) {
    asm volatile("ldmatrix.sync.aligned.m8n8.x4.shared.b16 {%0,%1,%2,%3}, [%4];"
        : "=r"(r[0]), "=r"(r[1]), "=r"(r[2]), "=r"(r[3]) : "r"(addr));
}
__device__ __forceinline__ void ldmx2(uint32_t* r, uint32_t addr) {
    asm volatile("ldmatrix.sync.aligned.m8n8.x2.shared.b16 {%0,%1}, [%2];"
        : "=r"(r[0]), "=r"(r[1]) : "r"(addr));
}
__device__ __forceinline__ void mma16816(float* c, const uint32_t* a, const uint32_t* b) {
    asm volatile("mma.sync.aligned.m16n8k16.row.col.f32.bf16.bf16.f32 "
        "{%0,%1,%2,%3}, {%4,%5,%6,%7}, {%8,%9}, {%0,%1,%2,%3};"
        : "+f"(c[0]), "+f"(c[1]), "+f"(c[2]), "+f"(c[3])
        : "r"(a[0]), "r"(a[1]), "r"(a[2]), "r"(a[3]), "r"(b[0]), "r"(b[1]));
}
__device__ __forceinline__ void mma_s8(int* c, const uint32_t* a, const uint32_t* b) {
    asm volatile("mma.sync.aligned.m16n8k32.row.col.s32.s8.s8.s32 "
        "{%0,%1,%2,%3}, {%4,%5,%6,%7}, {%8,%9}, {%0,%1,%2,%3};"
        : "+r"(c[0]), "+r"(c[1]), "+r"(c[2]), "+r"(c[3])
        : "r"(a[0]), "r"(a[1]), "r"(a[2]), "r"(a[3]), "r"(b[0]), "r"(b[1]));
}
#define CP_ASYNC16(dst, src) \
    asm volatile("cp.async.cg.shared.global [%0], [%1], 16;" :: "r"(dst), "l"(src))
#define CP_COMMIT   asm volatile("cp.async.commit_group;" ::: "memory")
#define CP_WAIT2    asm volatile("cp.async.wait_group 2;" ::: "memory")
#define CP_WAIT1    asm volatile("cp.async.wait_group 1;" ::: "memory")
#define CP_WAIT0    asm volatile("cp.async.wait_group 0;" ::: "memory")

// ---------------- fp32 -> (hi, lo) bf16 split (input GEMM path) ---------------
__global__ void split_f32_kernel(const float* __restrict__ src,
                                 __nv_bfloat16* __restrict__ hi,
                                 __nv_bfloat16* __restrict__ lo, int n4)
{
    int i = blockIdx.x * blockDim.x + threadIdx.x;
    if (i >= n4) return;
    float4 v = ((const float4*)src)[i];
    float f[4] = {v.x, v.y, v.z, v.w};
    uint32_t ph[2], pl[2];
#pragma unroll
    for (int q = 0; q < 2; q++) {
        __nv_bfloat16 h0 = __float2bfloat16(f[q * 2 + 0]);
        __nv_bfloat16 h1 = __float2bfloat16(f[q * 2 + 1]);
        __nv_bfloat16 l0 = __float2bfloat16(f[q * 2 + 0] - __bfloat162float(h0));
        __nv_bfloat16 l1 = __float2bfloat16(f[q * 2 + 1] - __bfloat162float(h1));
        ph[q] = (uint32_t)__bfloat16_as_ushort(h0) | ((uint32_t)__bfloat16_as_ushort(h1) << 16);
        pl[q] = (uint32_t)__bfloat16_as_ushort(l0) | ((uint32_t)__bfloat16_as_ushort(l1) << 16);
    }
    ((uint2*)hi)[i] = make_uint2(ph[0], ph[1]);
    ((uint2*)lo)[i] = make_uint2(pl[0], pl[1]);
}

// ---------------- fp32 -> int16 fixed -> (a, b) signed int8 planes ------------
__global__ void split_whh_i8(const float* __restrict__ W,
                             int8_t* __restrict__ wa, int8_t* __restrict__ wb, int n4)
{
    int i = blockIdx.x * blockDim.x + threadIdx.x;
    if (i >= n4) return;
    float4 v = ((const float4*)W)[i];
    float f[4] = {v.x, v.y, v.z, v.w};
    char4 a4, b4;
    char* ap = (char*)&a4;
    char* bp = (char*)&b4;
#pragma unroll
    for (int q = 0; q < 4; q++) {
        int wi = __float2int_rn(f[q] * WSCALE);
        wi = max(-32639, min(32639, wi));
        int a = (wi + 128) >> 8;
        ap[q] = (char)a;
        bp[q] = (char)(wi - (a << 8));
    }
    ((char4*)wa)[i] = a4;
    ((char4*)wb)[i] = b4;
}

// ---------------- HMMA bf16-split input GEMM (validated, unchanged) -----------
#define SROW 72
__global__ void __launch_bounds__(256, 1)
gemm_xg_hmma(const __nv_bfloat16* __restrict__ Xhi, const __nv_bfloat16* __restrict__ Xlo,
             const __nv_bfloat16* __restrict__ Whi, const __nv_bfloat16* __restrict__ Wlo,
             const float* __restrict__ bias, float* __restrict__ C)
{
    extern __shared__ __nv_bfloat16 sm[];
    const int TILE = 128 * SROW;

    const int tid  = threadIdx.x;
    const int lane = tid & 31;
    const int wid  = tid >> 5;
    const int wm   = wid & 1;
    const int wn   = wid >> 1;
    const int n0   = blockIdx.x * 128;
    const int m0   = blockIdx.y * 128;

    const uint32_t smb = smem_u32(sm);

    float acc[4][4][4];
#pragma unroll
    for (int i = 0; i < 4; i++)
#pragma unroll
        for (int j = 0; j < 4; j++)
#pragma unroll
            for (int q = 0; q < 4; q++) acc[i][j][q] = 0.f;

    const int arow = (wm * 64 + (lane & 15)) * SROW + (lane >> 4) * 8;
    const int brow = (wn * 32 + (lane & 7) + ((lane >> 4) << 3)) * SROW
                   + ((lane >> 3) & 1) * 8;

    const __nv_bfloat16* srcs[4] = {
        Xhi + (size_t)m0 * HH, Xlo + (size_t)m0 * HH,
        Whi + (size_t)n0 * HH, Wlo + (size_t)n0 * HH };

    for (int ch = 0; ch < 16; ch++) {
        const int kt = ch * 64;
#pragma unroll
        for (int tile = 0; tile < 4; tile++) {
            const __nv_bfloat16* src = srcs[tile] + kt;
#pragma unroll
            for (int it = 0; it < 4; it++) {
                int idx = tid + it * 256;
                int row = idx >> 3, c8 = idx & 7;
                float4 v = *(const float4*)(src + (size_t)row * HH + c8 * 8);
                *(float4*)(sm + tile * TILE + row * SROW + c8 * 8) = v;
            }
        }
        __syncthreads();

#pragma unroll
        for (int ks = 0; ks < 4; ks++) {
            uint32_t ahi[4][4], alo[4][4], bhi[4][2], blo[4][2];
#pragma unroll
            for (int mf = 0; mf < 4; mf++) {
                uint32_t aoff = (uint32_t)(arow + mf * 16 * SROW + ks * 16) * 2;
                ldmx4(ahi[mf], smb + 0 * TILE * 2 + aoff);
                ldmx4(alo[mf], smb + 1 * TILE * 2 + aoff);
            }
#pragma unroll
            for (int pr = 0; pr < 2; pr++) {
                uint32_t boff = (uint32_t)(brow + pr * 16 * SROW + ks * 16) * 2;
                uint32_t rh[4], rl[4];
                ldmx4(rh, smb + 2 * TILE * 2 + boff);
                ldmx4(rl, smb + 3 * TILE * 2 + boff);
                bhi[pr * 2 + 0][0] = rh[0]; bhi[pr * 2 + 0][1] = rh[1];
                bhi[pr * 2 + 1][0] = rh[2]; bhi[pr * 2 + 1][1] = rh[3];
                blo[pr * 2 + 0][0] = rl[0]; blo[pr * 2 + 0][1] = rl[1];
                blo[pr * 2 + 1][0] = rl[2]; blo[pr * 2 + 1][1] = rl[3];
            }
#pragma unroll
            for (int mf = 0; mf < 4; mf++)
#pragma unroll
                for (int nf = 0; nf < 4; nf++) {
                    mma16816(acc[mf][nf], ahi[mf], bhi[nf]);
                    mma16816(acc[mf][nf], ahi[mf], blo[nf]);
                    mma16816(acc[mf][nf], alo[mf], bhi[nf]);
                }
        }
        __syncthreads();
    }

#pragma unroll
    for (int mf = 0; mf < 4; mf++) {
        int row = m0 + wm * 64 + mf * 16 + (lane >> 2);
#pragma unroll
        for (int nf = 0; nf < 4; nf++) {
            int col = n0 + wn * 32 + nf * 8 + (lane & 3) * 2;
            float b0 = bias[col], b1 = bias[col + 1];
            float2 v0 = make_float2(acc[mf][nf][0] + b0, acc[mf][nf][1] + b1);
            float2 v1 = make_float2(acc[mf][nf][2] + b0, acc[mf][nf][3] + b1);
            *(float2*)&C[(size_t)row * G3 + col]       = v0;
            *(float2*)&C[(size_t)(row + 8) * G3 + col] = v1;
        }
    }
}

// ---------------- software grid barrier (RB blocks) ---------------------------
__device__ __forceinline__ void grid_bar()
{
    __threadfence();
    __syncthreads();
    if (threadIdx.x == 0) {
        unsigned gen = *(volatile unsigned*)&g_bar_gen;
        if (atomicAdd(&g_bar_count, 1u) == RB - 1) {
            g_bar_count = 0;
            __threadfence();
            *(volatile unsigned*)&g_bar_gen = gen + 1;
        } else {
            while (*(volatile unsigned*)&g_bar_gen == gen) __nanosleep(32);
        }
        __threadfence();
    }
    __syncthreads();
}

// ---------------- persistent int8 GRU recurrence ------------------------------
// Block bx owns j0 = bx*8. W smem: 24 rows (r8|z8|n8) x 1024 int8, a+b planes.
// Operands swapped vs v3: A = h (batches in m, 4 x m16), B = W rows (3 x n8) ->
// zero m-padding. Warp (mt = w&3, kh = w>>2): m-tile mt, k-half kh (within each
// chunk: kh=0 -> k 0-63, kh=1 -> k 64-127). k-halves reduced via accbuf.
__global__ void __launch_bounds__(256, 1)
gru_rec_i8(const float* __restrict__ h0,
           const int8_t* __restrict__ wa8, const int8_t* __restrict__ wb8,
           const float* __restrict__ bhh,
           const float* __restrict__ xg,     // [T,B,3H]
           float* __restrict__ Y,            // [T,B,H]
           float* __restrict__ hn,           // [B,H] or null
           int8_t* __restrict__ ha0, int8_t* __restrict__ hb0,
           int8_t* __restrict__ ha1, int8_t* __restrict__ hb1)
{
    extern __shared__ char smc[];
    float* accbuf = (float*)(smc + OFF8_ACC);           // [kh 2][batch 64][grow 26]
    const uint32_t smb   = smem_u32(smc);
    const uint32_t hbase = smb + OFF8_H;

    const int tid  = threadIdx.x;
    const int lane = tid & 31;
    const int w    = tid >> 5;
    const int mt   = w & 3;          // m-tile (batches mt*16..+16)
    const int kh   = w >> 2;         // k-half within chunk
    const int j0   = blockIdx.x * 8;

    // ---- preload W slice (24 rows x 1024 int8, both planes) ----
    for (int i = tid; i < 24 * 64; i += 256) {
        int p = i >> 6, seg = i & 63;
        size_t off = ((size_t)(p >> 3) * HH + j0 + (p & 7)) * HH + seg * 16;
        *(uint4*)(smc + p * WROW8 + seg * 16)            = *(const uint4*)(wa8 + off);
        *(uint4*)(smc + OFF8_WB + p * WROW8 + seg * 16)  = *(const uint4*)(wb8 + off);
    }

    // ---- h master in registers: thread owns (pb, j0+pj), (pb, j0+pj+1) ----
    const int pb = tid >> 2;
    const int pj = (tid & 3) * 2;
    float hm0 = h0[(size_t)pb * HH + j0 + pj];
    float hm1 = h0[(size_t)pb * HH + j0 + pj + 1];
    {
        int h16a = max(-32639, min(32639, __float2int_rn(hm0 * HSCALE)));
        int h16b = max(-32639, min(32639, __float2int_rn(hm1 * HSCALE)));
        int a0 = (h16a + 128) >> 8, a1 = (h16b + 128) >> 8;
        char2 ca, cb;
        ca.x = (char)a0;              ca.y = (char)a1;
        cb.x = (char)(h16a - (a0 << 8)); cb.y = (char)(h16b - (a1 << 8));
        *(char2*)&ha0[(size_t)pb * HH + j0 + pj] = ca;
        *(char2*)&hb0[(size_t)pb * HH + j0 + pj] = cb;
    }
    const float br0 = bhh[j0 + pj],          br1 = bhh[j0 + pj + 1];
    const float bz0 = bhh[HH + j0 + pj],     bz1 = bhh[HH + j0 + pj + 1];
    const float bn0 = bhh[2 * HH + j0 + pj], bn1 = bhh[2 * HH + j0 + pj + 1];

    grid_bar();

    // ldmatrix bases
    // A (h, m16k32): lanes 0-15 rows, lanes 16-31 same rows k+16B
    const uint32_t a_base = (uint32_t)((mt * 16 + (lane & 15)) * HROW8 + (lane >> 4) * 16);
    // B (W) x4 covering nt0+nt1: lanes 0-15 rows 0-7 (k+0/k+16), 16-31 rows 8-15
    const uint32_t b4_base = (uint32_t)((((lane >> 4) << 3) + (lane & 7)) * WROW8
                                        + ((lane >> 3) & 1) * 16);
    // B (W) x2 for nt2 (rows 16-23): lanes 0-15 supply addresses
    const uint32_t b2_base = (uint32_t)((16 + (lane & 7)) * WROW8 + ((lane >> 3) & 1) * 16);

    const float M1 = 65536.0f / (HSCALE * WSCALE);
    const float M2 = M1 / 256.0f;

    for (int t = 0; t < TT; t++) {
        const int8_t* sa = (t & 1) ? ha1 : ha0;
        const int8_t* sb = (t & 1) ? hb1 : hb0;

        // xg prefetch (hidden behind the chunk loop)
        const float* xrow = xg + ((size_t)t * BB + pb) * G3;
        float2 xr = *(const float2*)&xrow[j0 + pj];
        float2 xz = *(const float2*)&xrow[HH + j0 + pj];
        float2 xn = *(const float2*)&xrow[2 * HH + j0 + pj];

        int aa[3][4], ab[3][4];
#pragma unroll
        for (int nt = 0; nt < 3; nt++)
#pragma unroll
            for (int q = 0; q < 4; q++) { aa[nt][q] = 0; ab[nt][q] = 0; }

        // stage: one chunk = 64 b x 128 k x 2 planes = 16KB = 1024 cp.async
        auto stage = [&](int chunk, uint32_t bufo) {
            const int kt = chunk * 128;
#pragma unroll
            for (int i = 0; i < 4; i++) {
                int idx = tid + i * 256;
                int s = idx >> 9, rem = idx & 511, row = rem >> 3, seg = rem & 7;
                uint32_t dst = hbase + bufo + (uint32_t)s * 9216 + row * HROW8 + seg * 16;
                const int8_t* src = (s ? sb : sa) + (size_t)row * HH + kt + seg * 16;
                CP_ASYNC16(dst, src);
            }
            CP_COMMIT;
        };

        // 4-deep pipeline prologue
        stage(0, 0);
        stage(1, HBUF8);
        stage(2, 2 * HBUF8);

        for (int c = 0; c < 8; c++) {
            if (c < 6) { CP_WAIT2; } else if (c == 6) { CP_WAIT1; } else { CP_WAIT0; }
            __syncthreads();                         // chunk c visible; buf (c+3)&3 free
            if (c + 3 < 8) stage(c + 3, (uint32_t)((c + 3) & 3) * HBUF8);

            const uint32_t hb_ = hbase + (uint32_t)(c & 3) * HBUF8;
#pragma unroll
            for (int ks = 0; ks < 2; ks++) {
                const uint32_t kloc = (uint32_t)(kh * 64 + ks * 32);
                uint32_t har[4], hbr[4], wa01[4], wb01[4], wa2[2], wb2[2];
                ldmx4(har, hb_ + a_base + kloc);
                ldmx4(hbr, hb_ + 9216 + a_base + kloc);
                const uint32_t kg = (uint32_t)(c * 128) + kloc;
                ldmx4(wa01, smb + b4_base + kg);
                ldmx2(wa2,  smb + b2_base + kg);
                ldmx4(wb01, smb + OFF8_WB + b4_base + kg);
                ldmx2(wb2,  smb + OFF8_WB + b2_base + kg);
                mma_s8(aa[0], har, &wa01[0]);
                mma_s8(ab[0], har, &wb01[0]);
                mma_s8(ab[0], hbr, &wa01[0]);
                mma_s8(aa[1], har, &wa01[2]);
                mma_s8(ab[1], har, &wb01[2]);
                mma_s8(ab[1], hbr, &wa01[2]);
                mma_s8(aa[2], har, wa2);
                mma_s8(ab[2], har, wb2);
                mma_s8(ab[2], hbr, wa2);
            }
        }

        // ---- partial gate pre-activations -> accbuf (fp32, per k-half) ----
        {
            int r0 = mt * 16 + (lane >> 2);
            int cg = (lane & 3) * 2;
#pragma unroll
            for (int nt = 0; nt < 3; nt++) {
                int g0 = nt * 8 + cg;
                accbuf[(kh * 64 + r0) * 26 + g0]         = (float)aa[nt][0] * M1 + (float)ab[nt][0] * M2;
                accbuf[(kh * 64 + r0) * 26 + g0 + 1]     = (float)aa[nt][1] * M1 + (float)ab[nt][1] * M2;
                accbuf[(kh * 64 + r0 + 8) * 26 + g0]     = (float)aa[nt][2] * M1 + (float)ab[nt][2] * M2;
                accbuf[(kh * 64 + r0 + 8) * 26 + g0 + 1] = (float)aa[nt][3] * M1 + (float)ab[nt][3] * M2;
            }
        }
        __syncthreads();

        // ---- pointwise GRU update (k-half reduction inline) ----
        {
            float gr0 = accbuf[pb * 26 + pj]          + accbuf[(64 + pb) * 26 + pj];
            float gr1 = accbuf[pb * 26 + pj + 1]      + accbuf[(64 + pb) * 26 + pj + 1];
            float gz0 = accbuf[pb * 26 + 8 + pj]      + accbuf[(64 + pb) * 26 + 8 + pj];
            float gz1 = accbuf[pb * 26 + 9 + pj]      + accbuf[(64 + pb) * 26 + 9 + pj];
            float gn0 = accbuf[pb * 26 + 16 + pj]     + accbuf[(64 + pb) * 26 + 16 + pj];
            float gn1 = accbuf[pb * 26 + 17 + pj]     + accbuf[(64 + pb) * 26 + 17 + pj];

            float r0 = 1.f / (1.f + expf(-(xr.x + gr0 + br0)));
            float r1 = 1.f / (1.f + expf(-(xr.y + gr1 + br1)));
            float z0 = 1.f / (1.f + expf(-(xz.x + gz0 + bz0)));
            float z1 = 1.f / (1.f + expf(-(xz.y + gz1 + bz1)));
            float n0 = tanhf(xn.x + r0 * (gn0 + bn0));
            float n1 = tanhf(xn.y + r1 * (gn1 + bn1));
            hm0 = (1.f - z0) * n0 + z0 * hm0;
            hm1 = (1.f - z1) * n1 + z1 * hm1;

            int h16a = max(-32639, min(32639, __float2int_rn(hm0 * HSCALE)));
            int h16b = max(-32639, min(32639, __float2int_rn(hm1 * HSCALE)));
            int a0 = (h16a + 128) >> 8, a1 = (h16b + 128) >> 8;
            char2 ca, cb;
            ca.x = (char)a0;                 ca.y = (char)a1;
            cb.x = (char)(h16a - (a0 << 8)); cb.y = (char)(h16b - (a1 << 8));
            int8_t* da = (t & 1) ? ha0 : ha1;   // buffer (t+1)&1
            int8_t* db = (t & 1) ? hb0 : hb1;
            *(char2*)&da[(size_t)pb * HH + j0 + pj] = ca;
            *(char2*)&db[(size_t)pb * HH + j0 + pj] = cb;
            *(float2*)&Y[((size_t)t * BB + pb) * HH + j0 + pj] = make_float2(hm0, hm1);
        }

        grid_bar();
    }

    if (hn != nullptr)
        *(float2*)&hn[(size_t)pb * HH + j0 + pj] = make_float2(hm0, hm1);
}

// ---------------- launch -------------------------------------------------------
extern "C" void kernel_launch(void* const* d_in, const int* in_sizes, int n_in,
                              void* d_out, int out_size)
{
    const float* x   = (const float*)d_in[0];
    const float* h0  = (const float*)d_in[1];
    const float* Wih = (const float*)d_in[2];
    const float* Whh = (const float*)d_in[3];
    const float* bih = (const float*)d_in[4];
    const float* bhh = (const float*)d_in[5];
    float* out = (float*)d_out;

    float *xg, *y1;
    __nv_bfloat16 *xhi, *xlo, *whi, *wlo;
    int8_t *wa8, *wb8, *ha8, *hb8;
    cudaGetSymbolAddress((void**)&xg,  g_xg);
    cudaGetSymbolAddress((void**)&y1,  g_y1);
    cudaGetSymbolAddress((void**)&xhi, g_xhi);
    cudaGetSymbolAddress((void**)&xlo, g_xlo);
    cudaGetSymbolAddress((void**)&whi, g_whi);
    cudaGetSymbolAddress((void**)&wlo, g_wlo);
    cudaGetSymbolAddress((void**)&wa8, g_wa8);
    cudaGetSymbolAddress((void**)&wb8, g_wb8);
    cudaGetSymbolAddress((void**)&ha8, g_ha8);
    cudaGetSymbolAddress((void**)&hb8, g_hb8);

    const int gemmSmem = 4 * 128 * SROW * 2;     // 73728 B
    static bool attr_set = false;
    if (!attr_set) {
        cudaFuncSetAttribute(gemm_xg_hmma,
                             cudaFuncAttributeMaxDynamicSharedMemorySize, gemmSmem);
        cudaFuncSetAttribute(gru_rec_i8,
                             cudaFuncAttributeMaxDynamicSharedMemorySize, SMEM8);
        attr_set = true;
    }

    const dim3 gemmGrid(G3 / 128, (TT * BB) / 128);   // 24 x 256
    const int  n4x = TT * BB * HH / 4;
    const int  n4w = G3 * HH / 4;
    const bool write_hn = (out_size >= TT * BB * HH + LL * BB * HH);

    bar_reset_kernel<<<1, 1>>>();

    for (int l = 0; l < LL; l++) {
        const float* Xin = (l == 0) ? x : y1;
        float* Y         = (l == 0) ? y1 : out;
        float* hn        = write_hn
            ? out + (size_t)TT * BB * HH + (size_t)l * BB * HH : nullptr;

        split_f32_kernel<<<(n4x + 255) / 256, 256>>>(Xin, xhi, xlo, n4x);
        split_f32_kernel<<<(n4w + 255) / 256, 256>>>(Wih + (size_t)l * G3 * HH,
                                                     whi, wlo, n4w);
        split_whh_i8<<<(n4w + 255) / 256, 256>>>(Whh + (size_t)l * G3 * HH,
                                                 wa8, wb8, n4w);

        gemm_xg_hmma<<<gemmGrid, 256, gemmSmem>>>(xhi, xlo, whi, wlo,
                                                  bih + (size_t)l * G3, xg);

        gru_rec_i8<<<RB, 256, SMEM8>>>(h0 + (size_t)l * BB * HH,
                                       wa8, wb8, bhh + (size_t)l * G3,
                                       xg, Y, hn,
                                       ha8, hb8,
                                       ha8 + BB * HH, hb8 + BB * HH);
    }
}